// round 1
// baseline (speedup 1.0000x reference)
#include <cuda_runtime.h>
#include <cstdint>

#define N_NODES 100000
#define IN_DIM  256
#define OUT_DIM 64
#define N_SUP   2
#define N_EDGES 1600000

// Scratch: pre_sup[s][n][64]  (51.2 MB, static device allocation — allowed)
__device__ float g_presup[(size_t)N_SUP * N_NODES * OUT_DIM];

// ---------------------------------------------------------------------------
// Kernel 1: zero the output (d_out is poisoned before timing)
// ---------------------------------------------------------------------------
__global__ void zero_kernel(float* __restrict__ out, int n) {
    int i = blockIdx.x * blockDim.x + threadIdx.x;
    if (i < n) out[i] = 0.0f;
}

// ---------------------------------------------------------------------------
// Kernel 2: GEMM  PS[s] = X @ W[s]
// Tiled fp32: BM=64, BN=64, BK=16, 256 threads, 4x4 per thread.
// grid = (ceil(N/64), N_SUP)
// ---------------------------------------------------------------------------
#define BM 64
#define BN 64
#define BK 16

__global__ __launch_bounds__(256)
void gemm_kernel(const float* __restrict__ X, const float* __restrict__ W,
                 float* __restrict__ PS) {
    const int s = blockIdx.y;
    const int rowBase = blockIdx.x * BM;
    const float* Wp = W + (size_t)s * IN_DIM * OUT_DIM;

    __shared__ float As[BK][BM];   // A tile, transposed: As[k][m]
    __shared__ float Bs[BK][BN];   // B tile: Bs[k][n]

    const int tid = threadIdx.x;        // 0..255
    const int tx = tid & 15;            // 0..15 -> col group
    const int ty = tid >> 4;            // 0..15 -> row group

    // A-load mapping: thread t loads float4 from X[rowBase + t/4][k0 + (t%4)*4]
    const int a_r  = tid >> 2;          // 0..63
    const int a_c4 = (tid & 3) * 4;     // 0,4,8,12
    // B-load mapping: thread t loads float4 from W[k0 + t/16][(t%16)*4]
    const int b_r  = tid >> 4;          // 0..15
    const int b_c4 = (tid & 15) * 4;    // 0..60

    float acc[4][4] = {};

    for (int k0 = 0; k0 < IN_DIM; k0 += BK) {
        // ---- load A tile ----
        {
            int grow = rowBase + a_r;
            float4 v = make_float4(0.f, 0.f, 0.f, 0.f);
            if (grow < N_NODES) {
                v = *reinterpret_cast<const float4*>(X + (size_t)grow * IN_DIM + k0 + a_c4);
            }
            As[a_c4 + 0][a_r] = v.x;
            As[a_c4 + 1][a_r] = v.y;
            As[a_c4 + 2][a_r] = v.z;
            As[a_c4 + 3][a_r] = v.w;
        }
        // ---- load B tile ----
        {
            float4 v = *reinterpret_cast<const float4*>(Wp + (size_t)(k0 + b_r) * OUT_DIM + b_c4);
            Bs[b_r][b_c4 + 0] = v.x;
            Bs[b_r][b_c4 + 1] = v.y;
            Bs[b_r][b_c4 + 2] = v.z;
            Bs[b_r][b_c4 + 3] = v.w;
        }
        __syncthreads();

        #pragma unroll
        for (int kk = 0; kk < BK; kk++) {
            float a[4], b[4];
            #pragma unroll
            for (int i = 0; i < 4; i++) a[i] = As[kk][ty * 4 + i];
            #pragma unroll
            for (int j = 0; j < 4; j++) b[j] = Bs[kk][tx * 4 + j];
            #pragma unroll
            for (int i = 0; i < 4; i++)
                #pragma unroll
                for (int j = 0; j < 4; j++)
                    acc[i][j] = fmaf(a[i], b[j], acc[i][j]);
        }
        __syncthreads();
    }

    // ---- store 4x4 (cols contiguous -> float4) ----
    #pragma unroll
    for (int i = 0; i < 4; i++) {
        int grow = rowBase + ty * 4 + i;
        if (grow < N_NODES) {
            float4 v = make_float4(acc[i][0], acc[i][1], acc[i][2], acc[i][3]);
            *reinterpret_cast<float4*>(
                PS + ((size_t)s * N_NODES + grow) * OUT_DIM + tx * 4) = v;
        }
    }
}

// ---------------------------------------------------------------------------
// Kernel 3: SpMM scatter.  16 threads per edge, each handles a float4 slice.
// out[dst] += val * PS[s][src]   (vector red.global.add.v4.f32)
// grid = (ceil(E*16/256), N_SUP)
// ---------------------------------------------------------------------------
__global__ __launch_bounds__(256)
void spmm_kernel(const float* __restrict__ PS,
                 const float* __restrict__ edge_val,
                 const int*   __restrict__ edge_src,
                 const int*   __restrict__ edge_dst,
                 float* __restrict__ out) {
    const int s = blockIdx.y;
    long long gid = (long long)blockIdx.x * blockDim.x + threadIdx.x;
    const int lane = (int)(gid & 15);          // 0..15, float4 slice within row
    const long long e = gid >> 4;
    if (e >= N_EDGES) return;

    const long long base = (long long)s * N_EDGES + e;
    const float w  = edge_val[base];
    const int   sr = edge_src[base];
    const int   ds = edge_dst[base];

    const float4 m = reinterpret_cast<const float4*>(
        PS + ((size_t)s * N_NODES + sr) * OUT_DIM)[lane];

    float4 r;
    r.x = m.x * w; r.y = m.y * w; r.z = m.z * w; r.w = m.w * w;

    float* o = out + (size_t)ds * OUT_DIM + lane * 4;
    asm volatile("red.global.add.v4.f32 [%0], {%1, %2, %3, %4};"
                 :: "l"(o), "f"(r.x), "f"(r.y), "f"(r.z), "f"(r.w)
                 : "memory");
}

// ---------------------------------------------------------------------------
// Kernel 4: in-place ReLU
// ---------------------------------------------------------------------------
__global__ void relu_kernel(float* __restrict__ out, int n) {
    int i = blockIdx.x * blockDim.x + threadIdx.x;
    if (i < n) {
        float v = out[i];
        out[i] = v > 0.0f ? v : 0.0f;
    }
}

// ---------------------------------------------------------------------------
// Launch
// ---------------------------------------------------------------------------
extern "C" void kernel_launch(void* const* d_in, const int* in_sizes, int n_in,
                              void* d_out, int out_size) {
    const float* x        = (const float*)d_in[0];   // [N, 256]
    const float* W        = (const float*)d_in[1];   // [2, 256, 64]
    const float* edge_val = (const float*)d_in[2];   // [2, E]
    const int*   edge_src = (const int*)  d_in[3];   // [2, E]
    const int*   edge_dst = (const int*)  d_in[4];   // [2, E]
    float* out = (float*)d_out;                      // [N, 64]

    float* PS;
    cudaGetSymbolAddress((void**)&PS, g_presup);

    const int out_elems = N_NODES * OUT_DIM;

    // zero output
    zero_kernel<<<(out_elems + 255) / 256, 256>>>(out, out_elems);

    // GEMM: pre_sup[s] = x @ W[s]
    dim3 ggrid((N_NODES + BM - 1) / BM, N_SUP);
    gemm_kernel<<<ggrid, 256>>>(x, W, PS);

    // SpMM scatter-add
    long long spmm_threads = (long long)N_EDGES * 16;
    dim3 sgrid((unsigned)((spmm_threads + 255) / 256), N_SUP);
    spmm_kernel<<<sgrid, 256>>>(PS, edge_val, edge_src, edge_dst, out);

    // ReLU
    relu_kernel<<<(out_elems + 255) / 256, 256>>>(out, out_elems);
}

// round 3
// speedup vs baseline: 1.3193x; 1.3193x over previous
#include <cuda_runtime.h>
#include <cuda_bf16.h>
#include <cstdint>

#define N_NODES 100000
#define IN_DIM  256
#define OUT_DIM 64
#define N_SUP   2
#define N_EDGES 1600000

// pre_sup[s][n][64]  (51.2 MB scratch)
__device__ float g_presup[(size_t)N_SUP * N_NODES * OUT_DIM];
// W in mma.sync B-fragment layout: [s][ntile(8)][kstep(16)][lane(32)] -> uint4{bH0,bH1,bL0,bL1}
__device__ uint4 g_Wfrag[N_SUP * 8 * 16 * 32];   // 128 KB

__device__ __forceinline__ uint32_t pack_bf2(__nv_bfloat16 lo, __nv_bfloat16 hi) {
    return ((uint32_t)__bfloat16_as_ushort(hi) << 16) | (uint32_t)__bfloat16_as_ushort(lo);
}

// ---------------------------------------------------------------------------
// Prep: W[s][k][n] fp32 -> bf16 hi/lo B fragments for mma.sync.m16n8k16.row.col
// b0 = {B[k0+0][n], B[k0+1][n]}, b1 = {B[k0+8][n], B[k0+9][n]},
// k0 = kstep*16 + (lane&3)*2, n = ntile*8 + (lane>>2)
// ---------------------------------------------------------------------------
__global__ void wfrag_kernel(const float* __restrict__ W) {
    int t = blockIdx.x * blockDim.x + threadIdx.x;   // 8192
    if (t >= N_SUP * 8 * 16 * 32) return;
    int lane  = t & 31;
    int kstep = (t >> 5) & 15;
    int ntile = (t >> 9) & 7;
    int s     = t >> 12;
    int n  = ntile * 8 + (lane >> 2);
    int k0 = kstep * 16 + (lane & 3) * 2;

    float v00 = W[((size_t)s * IN_DIM + k0 + 0) * OUT_DIM + n];
    float v01 = W[((size_t)s * IN_DIM + k0 + 1) * OUT_DIM + n];
    float v10 = W[((size_t)s * IN_DIM + k0 + 8) * OUT_DIM + n];
    float v11 = W[((size_t)s * IN_DIM + k0 + 9) * OUT_DIM + n];

    __nv_bfloat16 h00 = __float2bfloat16_rn(v00), h01 = __float2bfloat16_rn(v01);
    __nv_bfloat16 h10 = __float2bfloat16_rn(v10), h11 = __float2bfloat16_rn(v11);
    __nv_bfloat16 l00 = __float2bfloat16_rn(v00 - __bfloat162float(h00));
    __nv_bfloat16 l01 = __float2bfloat16_rn(v01 - __bfloat162float(h01));
    __nv_bfloat16 l10 = __float2bfloat16_rn(v10 - __bfloat162float(h10));
    __nv_bfloat16 l11 = __float2bfloat16_rn(v11 - __bfloat162float(h11));

    uint4 o;
    o.x = pack_bf2(h00, h01);
    o.y = pack_bf2(h10, h11);
    o.z = pack_bf2(l00, l01);
    o.w = pack_bf2(l10, l11);
    g_Wfrag[t] = o;
}

// ---------------------------------------------------------------------------
// GEMM via mma.sync.m16n8k16 bf16, 3-pass hi/lo split.
// Warp = 16 rows x 64 cols x both supports. CTA = 8 warps (128 rows).
// ---------------------------------------------------------------------------
__device__ __forceinline__ void mma16816(float d[4], const uint32_t a[4],
                                         uint32_t b0, uint32_t b1) {
    asm volatile(
        "mma.sync.aligned.m16n8k16.row.col.f32.bf16.bf16.f32 "
        "{%0,%1,%2,%3}, {%4,%5,%6,%7}, {%8,%9}, {%0,%1,%2,%3};"
        : "+f"(d[0]), "+f"(d[1]), "+f"(d[2]), "+f"(d[3])
        : "r"(a[0]), "r"(a[1]), "r"(a[2]), "r"(a[3]), "r"(b0), "r"(b1));
}

#define WFRAG_ELEMS (N_SUP * 8 * 16 * 32)
#define SMEM_SZ (WFRAG_ELEMS * 16)

__global__ __launch_bounds__(256)
void gemm_mma_kernel(const float* __restrict__ X, float* __restrict__ PS) {
    extern __shared__ uint4 wfrag[];
    const int tid = threadIdx.x;

    // copy W fragments (128 KB) to smem
    #pragma unroll 8
    for (int i = tid; i < WFRAG_ELEMS; i += 256) wfrag[i] = g_Wfrag[i];
    __syncthreads();

    const int warp = tid >> 5;
    const int lane = tid & 31;
    const long long wtile = (long long)blockIdx.x * 8 + warp;
    const long long rowBase = wtile * 16;
    if (rowBase >= N_NODES) return;    // 100000 % 16 == 0 -> in-bounds tiles only

    const int rlo = lane >> 2;                 // 0..7
    const int kc  = (lane & 3) * 2;            // 0,2,4,6
    const float* x0 = X + (size_t)(rowBase + rlo) * IN_DIM + kc;

    float d[2][8][4];
    #pragma unroll
    for (int s = 0; s < 2; s++)
        #pragma unroll
        for (int n = 0; n < 8; n++)
            #pragma unroll
            for (int j = 0; j < 4; j++) d[s][n][j] = 0.f;

    #pragma unroll 4
    for (int ks = 0; ks < 16; ks++) {
        const float* xp = x0 + ks * 16;
        // A fragment sources: (row, col) = (r, kc), (r+8, kc), (r, kc+8), (r+8, kc+8)
        float2 v0 = *(const float2*)(xp);
        float2 v1 = *(const float2*)(xp + (size_t)8 * IN_DIM);
        float2 v2 = *(const float2*)(xp + 8);
        float2 v3 = *(const float2*)(xp + (size_t)8 * IN_DIM + 8);

        uint32_t ah[4], al[4];
        {
            float f[8] = {v0.x, v0.y, v1.x, v1.y, v2.x, v2.y, v3.x, v3.y};
            __nv_bfloat16 h[8], l[8];
            #pragma unroll
            for (int i = 0; i < 8; i++) {
                h[i] = __float2bfloat16_rn(f[i]);
                l[i] = __float2bfloat16_rn(f[i] - __bfloat162float(h[i]));
            }
            #pragma unroll
            for (int i = 0; i < 4; i++) {
                ah[i] = pack_bf2(h[i * 2], h[i * 2 + 1]);
                al[i] = pack_bf2(l[i * 2], l[i * 2 + 1]);
            }
        }

        #pragma unroll
        for (int s = 0; s < 2; s++) {
            #pragma unroll
            for (int n = 0; n < 8; n++) {
                uint4 b = wfrag[(((s * 8 + n) * 16) + ks) * 32 + lane];
                mma16816(d[s][n], ah, b.x, b.y);   // Ah * Bh
                mma16816(d[s][n], ah, b.z, b.w);   // Ah * Bl
                mma16816(d[s][n], al, b.x, b.y);   // Al * Bh
            }
        }
    }

    // Epilogue: c0,c1 -> (rowBase+rlo, n*8+kc), c2,c3 -> (+8 rows)
    #pragma unroll
    for (int s = 0; s < 2; s++) {
        float* base = PS + ((size_t)s * N_NODES + rowBase + rlo) * OUT_DIM + kc;
        #pragma unroll
        for (int n = 0; n < 8; n++) {
            *(float2*)(base + n * 8)                         = make_float2(d[s][n][0], d[s][n][1]);
            *(float2*)(base + n * 8 + (size_t)8 * OUT_DIM)   = make_float2(d[s][n][2], d[s][n][3]);
        }
    }
}

// ---------------------------------------------------------------------------
// zero / relu (float4)
// ---------------------------------------------------------------------------
__global__ void zero4_kernel(float4* __restrict__ out, int n4) {
    int i = blockIdx.x * blockDim.x + threadIdx.x;
    if (i < n4) out[i] = make_float4(0.f, 0.f, 0.f, 0.f);
}
__global__ void relu4_kernel(float4* __restrict__ out, int n4) {
    int i = blockIdx.x * blockDim.x + threadIdx.x;
    if (i < n4) {
        float4 v = out[i];
        v.x = fmaxf(v.x, 0.f); v.y = fmaxf(v.y, 0.f);
        v.z = fmaxf(v.z, 0.f); v.w = fmaxf(v.w, 0.f);
        out[i] = v;
    }
}

// ---------------------------------------------------------------------------
// SpMM scatter: 16 threads per edge, float4 slices, vector red.global
// ---------------------------------------------------------------------------
__global__ __launch_bounds__(256)
void spmm_kernel(const float* __restrict__ PS,
                 const float* __restrict__ edge_val,
                 const int*   __restrict__ edge_src,
                 const int*   __restrict__ edge_dst,
                 float* __restrict__ out) {
    const int s = blockIdx.y;
    long long gid = (long long)blockIdx.x * blockDim.x + threadIdx.x;
    const int lane = (int)(gid & 15);
    const long long e = gid >> 4;
    if (e >= N_EDGES) return;

    const long long base = (long long)s * N_EDGES + e;
    const float w  = edge_val[base];
    const int   sr = edge_src[base];
    const int   ds = edge_dst[base];

    const float4 m = reinterpret_cast<const float4*>(
        PS + ((size_t)s * N_NODES + sr) * OUT_DIM)[lane];

    float4 r;
    r.x = m.x * w; r.y = m.y * w; r.z = m.z * w; r.w = m.w * w;

    float* o = out + (size_t)ds * OUT_DIM + lane * 4;
    asm volatile("red.global.add.v4.f32 [%0], {%1, %2, %3, %4};"
                 :: "l"(o), "f"(r.x), "f"(r.y), "f"(r.z), "f"(r.w)
                 : "memory");
}

// ---------------------------------------------------------------------------
// Launch
// ---------------------------------------------------------------------------
extern "C" void kernel_launch(void* const* d_in, const int* in_sizes, int n_in,
                              void* d_out, int out_size) {
    const float* x        = (const float*)d_in[0];
    const float* W        = (const float*)d_in[1];
    const float* edge_val = (const float*)d_in[2];
    const int*   edge_src = (const int*)  d_in[3];
    const int*   edge_dst = (const int*)  d_in[4];
    float* out = (float*)d_out;

    float* PS;
    cudaGetSymbolAddress((void**)&PS, g_presup);

    static bool attr_set = false;
    if (!attr_set) {
        cudaFuncSetAttribute(gemm_mma_kernel,
                             cudaFuncAttributeMaxDynamicSharedMemorySize, SMEM_SZ);
        attr_set = true;
    }

    const int out_elems = N_NODES * OUT_DIM;
    const int n4 = out_elems / 4;

    zero4_kernel<<<(n4 + 255) / 256, 256>>>((float4*)out, n4);
    wfrag_kernel<<<(WFRAG_ELEMS + 255) / 256, 256>>>(W);

    const int n_wtiles = N_NODES / 16;                    // 6250
    const int n_ctas   = (n_wtiles + 7) / 8;              // 782
    gemm_mma_kernel<<<n_ctas, 256, SMEM_SZ>>>(x, PS);

    long long spmm_threads = (long long)N_EDGES * 16;
    dim3 sgrid((unsigned)((spmm_threads + 255) / 256), N_SUP);
    spmm_kernel<<<sgrid, 256>>>(PS, edge_val, edge_src, edge_dst, out);

    relu4_kernel<<<(n4 + 255) / 256, 256>>>((float4*)out, n4);
}

// round 4
// speedup vs baseline: 1.7385x; 1.3178x over previous
#include <cuda_runtime.h>
#include <cuda_bf16.h>
#include <cstdint>

#define N_NODES 100000
#define IN_DIM  256
#define OUT_DIM 64
#define N_SUP   2
#define N_EDGES 1600000
#define TOT_E   (N_SUP * N_EDGES)      // 3,200,000

#define SCAN_BLOCKS 100
#define CHUNK       1000               // SCAN_BLOCKS * CHUNK = 100000 = N_NODES

// ---------------------------------------------------------------------------
// Scratch (static device allocations)
// ---------------------------------------------------------------------------
__device__ float g_presup[(size_t)N_SUP * N_NODES * OUT_DIM];   // 51.2 MB
__device__ uint4 g_Wfrag[N_SUP * 8 * 16 * 32];                  // 128 KB
__device__ int   g_counts[N_NODES];
__device__ int   g_rowstart[N_NODES + 1];
__device__ int   g_cursor[N_NODES];
__device__ int   g_partials[SCAN_BLOCKS];
__device__ uint2 g_payload[TOT_E];                              // 25.6 MB

__device__ __forceinline__ uint32_t pack_bf2(__nv_bfloat16 lo, __nv_bfloat16 hi) {
    return ((uint32_t)__bfloat16_as_ushort(hi) << 16) | (uint32_t)__bfloat16_as_ushort(lo);
}

// ---------------------------------------------------------------------------
// W -> bf16 hi/lo mma.sync B fragments
// ---------------------------------------------------------------------------
__global__ void wfrag_kernel(const float* __restrict__ W) {
    int t = blockIdx.x * blockDim.x + threadIdx.x;   // 8192
    if (t >= N_SUP * 8 * 16 * 32) return;
    int lane  = t & 31;
    int kstep = (t >> 5) & 15;
    int ntile = (t >> 9) & 7;
    int s     = t >> 12;
    int n  = ntile * 8 + (lane >> 2);
    int k0 = kstep * 16 + (lane & 3) * 2;

    float v00 = W[((size_t)s * IN_DIM + k0 + 0) * OUT_DIM + n];
    float v01 = W[((size_t)s * IN_DIM + k0 + 1) * OUT_DIM + n];
    float v10 = W[((size_t)s * IN_DIM + k0 + 8) * OUT_DIM + n];
    float v11 = W[((size_t)s * IN_DIM + k0 + 9) * OUT_DIM + n];

    __nv_bfloat16 h00 = __float2bfloat16_rn(v00), h01 = __float2bfloat16_rn(v01);
    __nv_bfloat16 h10 = __float2bfloat16_rn(v10), h11 = __float2bfloat16_rn(v11);
    __nv_bfloat16 l00 = __float2bfloat16_rn(v00 - __bfloat162float(h00));
    __nv_bfloat16 l01 = __float2bfloat16_rn(v01 - __bfloat162float(h01));
    __nv_bfloat16 l10 = __float2bfloat16_rn(v10 - __bfloat162float(h10));
    __nv_bfloat16 l11 = __float2bfloat16_rn(v11 - __bfloat162float(h11));

    uint4 o;
    o.x = pack_bf2(h00, h01);
    o.y = pack_bf2(h10, h11);
    o.z = pack_bf2(l00, l01);
    o.w = pack_bf2(l10, l11);
    g_Wfrag[t] = o;
}

// ---------------------------------------------------------------------------
// GEMM via mma.sync.m16n8k16 bf16, 3-pass hi/lo split (unchanged from R3)
// ---------------------------------------------------------------------------
__device__ __forceinline__ void mma16816(float d[4], const uint32_t a[4],
                                         uint32_t b0, uint32_t b1) {
    asm volatile(
        "mma.sync.aligned.m16n8k16.row.col.f32.bf16.bf16.f32 "
        "{%0,%1,%2,%3}, {%4,%5,%6,%7}, {%8,%9}, {%0,%1,%2,%3};"
        : "+f"(d[0]), "+f"(d[1]), "+f"(d[2]), "+f"(d[3])
        : "r"(a[0]), "r"(a[1]), "r"(a[2]), "r"(a[3]), "r"(b0), "r"(b1));
}

#define WFRAG_ELEMS (N_SUP * 8 * 16 * 32)
#define SMEM_SZ (WFRAG_ELEMS * 16)

__global__ __launch_bounds__(256)
void gemm_mma_kernel(const float* __restrict__ X, float* __restrict__ PS) {
    extern __shared__ uint4 wfrag[];
    const int tid = threadIdx.x;

    #pragma unroll 8
    for (int i = tid; i < WFRAG_ELEMS; i += 256) wfrag[i] = g_Wfrag[i];
    __syncthreads();

    const int warp = tid >> 5;
    const int lane = tid & 31;
    const long long wtile = (long long)blockIdx.x * 8 + warp;
    const long long rowBase = wtile * 16;
    if (rowBase >= N_NODES) return;

    const int rlo = lane >> 2;
    const int kc  = (lane & 3) * 2;
    const float* x0 = X + (size_t)(rowBase + rlo) * IN_DIM + kc;

    float d[2][8][4];
    #pragma unroll
    for (int s = 0; s < 2; s++)
        #pragma unroll
        for (int n = 0; n < 8; n++)
            #pragma unroll
            for (int j = 0; j < 4; j++) d[s][n][j] = 0.f;

    #pragma unroll 4
    for (int ks = 0; ks < 16; ks++) {
        const float* xp = x0 + ks * 16;
        float2 v0 = *(const float2*)(xp);
        float2 v1 = *(const float2*)(xp + (size_t)8 * IN_DIM);
        float2 v2 = *(const float2*)(xp + 8);
        float2 v3 = *(const float2*)(xp + (size_t)8 * IN_DIM + 8);

        uint32_t ah[4], al[4];
        {
            float f[8] = {v0.x, v0.y, v1.x, v1.y, v2.x, v2.y, v3.x, v3.y};
            __nv_bfloat16 h[8], l[8];
            #pragma unroll
            for (int i = 0; i < 8; i++) {
                h[i] = __float2bfloat16_rn(f[i]);
                l[i] = __float2bfloat16_rn(f[i] - __bfloat162float(h[i]));
            }
            #pragma unroll
            for (int i = 0; i < 4; i++) {
                ah[i] = pack_bf2(h[i * 2], h[i * 2 + 1]);
                al[i] = pack_bf2(l[i * 2], l[i * 2 + 1]);
            }
        }

        #pragma unroll
        for (int s = 0; s < 2; s++) {
            #pragma unroll
            for (int n = 0; n < 8; n++) {
                uint4 b = wfrag[(((s * 8 + n) * 16) + ks) * 32 + lane];
                mma16816(d[s][n], ah, b.x, b.y);
                mma16816(d[s][n], ah, b.z, b.w);
                mma16816(d[s][n], al, b.x, b.y);
            }
        }
    }

    #pragma unroll
    for (int s = 0; s < 2; s++) {
        float* base = PS + ((size_t)s * N_NODES + rowBase + rlo) * OUT_DIM + kc;
        #pragma unroll
        for (int n = 0; n < 8; n++) {
            *(float2*)(base + n * 8)                       = make_float2(d[s][n][0], d[s][n][1]);
            *(float2*)(base + n * 8 + (size_t)8 * OUT_DIM) = make_float2(d[s][n][2], d[s][n][3]);
        }
    }
}

// ---------------------------------------------------------------------------
// CSR build: zero counts -> histogram -> scan (3 kernels) -> scatter payloads
// ---------------------------------------------------------------------------
__global__ void zero_counts_kernel(int* __restrict__ counts) {
    int i = blockIdx.x * blockDim.x + threadIdx.x;
    if (i < N_NODES) counts[i] = 0;
}

__global__ void hist_kernel(const int* __restrict__ edge_dst, int* __restrict__ counts) {
    int e = blockIdx.x * blockDim.x + threadIdx.x;
    if (e < TOT_E) atomicAdd(&counts[edge_dst[e]], 1);
}

__global__ void scan_block_sums(const int* __restrict__ counts, int* __restrict__ partials) {
    __shared__ int sm[256];
    int b = blockIdx.x;
    int sum = 0;
    for (int i = threadIdx.x; i < CHUNK; i += 256) sum += counts[b * CHUNK + i];
    sm[threadIdx.x] = sum;
    __syncthreads();
    for (int s = 128; s > 0; s >>= 1) {
        if (threadIdx.x < s) sm[threadIdx.x] += sm[threadIdx.x + s];
        __syncthreads();
    }
    if (threadIdx.x == 0) partials[b] = sm[0];
}

__global__ void scan_partials_kernel(int* __restrict__ partials) {
    __shared__ int bufA[128], bufB[128];
    int t = threadIdx.x;
    bufA[t] = (t < SCAN_BLOCKS) ? partials[t] : 0;
    __syncthreads();
    int* in = bufA; int* out = bufB;
    for (int off = 1; off < 128; off <<= 1) {
        out[t] = in[t] + (t >= off ? in[t - off] : 0);
        __syncthreads();
        int* tmp = in; in = out; out = tmp;
    }
    if (t < SCAN_BLOCKS) partials[t] = t ? in[t - 1] : 0;   // exclusive
}

__global__ __launch_bounds__(1024)
void scan_final_kernel(const int* __restrict__ counts, const int* __restrict__ partials,
                       int* __restrict__ rowstart, int* __restrict__ cursor) {
    __shared__ int bufA[1024], bufB[1024];
    int b = blockIdx.x, t = threadIdx.x;
    int g = b * CHUNK + t;
    bufA[t] = (t < CHUNK) ? counts[g] : 0;
    __syncthreads();
    int* in = bufA; int* out = bufB;
    for (int off = 1; off < 1024; off <<= 1) {
        out[t] = in[t] + (t >= off ? in[t - off] : 0);
        __syncthreads();
        int* tmp = in; in = out; out = tmp;
    }
    if (t < CHUNK) {
        int ex = partials[b] + (t ? in[t - 1] : 0);
        rowstart[g] = ex;
        cursor[g]   = ex;
    }
    if (b == SCAN_BLOCKS - 1 && t == CHUNK - 1)
        rowstart[N_NODES] = partials[b] + in[t];
}

__global__ void scatter_kernel(const float* __restrict__ edge_val,
                               const int*   __restrict__ edge_src,
                               const int*   __restrict__ edge_dst,
                               int* __restrict__ cursor,
                               uint2* __restrict__ payload) {
    int e = blockIdx.x * blockDim.x + threadIdx.x;
    if (e >= TOT_E) return;
    int d   = edge_dst[e];
    int pos = atomicAdd(&cursor[d], 1);
    int idx = edge_src[e] + ((e >= N_EDGES) ? N_NODES : 0);
    payload[pos] = make_uint2((unsigned)idx, __float_as_uint(edge_val[e]));
}

// ---------------------------------------------------------------------------
// Gather: one warp per node. Lanes 0-15 handle even edges, 16-31 odd edges;
// each lane owns a float4 slice. Combine halves via shfl, fused ReLU, one store.
// ---------------------------------------------------------------------------
__global__ __launch_bounds__(256)
void gather_kernel(const float* __restrict__ PS,
                   const int*   __restrict__ rowstart,
                   const uint2* __restrict__ payload,
                   float* __restrict__ out) {
    const int v = (blockIdx.x * 256 + threadIdx.x) >> 5;
    if (v >= N_NODES) return;
    const int lane = threadIdx.x & 31;
    const int half = lane >> 4;
    const int sl   = lane & 15;

    const int beg = rowstart[v];
    const int end = rowstart[v + 1];

    float4 acc = make_float4(0.f, 0.f, 0.f, 0.f);

    int j = beg + half;
    if (j < end) {
        uint2 p = payload[j];                       // prefetch first
        for (; j < end; j += 2) {
            uint2 pn;
            if (j + 2 < end) pn = payload[j + 2];   // prefetch next
            const float w = __uint_as_float(p.y);
            const float4 m = *(const float4*)(PS + (size_t)p.x * OUT_DIM + sl * 4);
            acc.x = fmaf(w, m.x, acc.x);
            acc.y = fmaf(w, m.y, acc.y);
            acc.z = fmaf(w, m.z, acc.z);
            acc.w = fmaf(w, m.w, acc.w);
            p = pn;
        }
    }

    // combine the two halves
    acc.x += __shfl_xor_sync(0xFFFFFFFFu, acc.x, 16);
    acc.y += __shfl_xor_sync(0xFFFFFFFFu, acc.y, 16);
    acc.z += __shfl_xor_sync(0xFFFFFFFFu, acc.z, 16);
    acc.w += __shfl_xor_sync(0xFFFFFFFFu, acc.w, 16);

    if (half == 0) {
        float4 r = make_float4(fmaxf(acc.x, 0.f), fmaxf(acc.y, 0.f),
                               fmaxf(acc.z, 0.f), fmaxf(acc.w, 0.f));
        *(float4*)(out + (size_t)v * OUT_DIM + sl * 4) = r;
    }
}

// ---------------------------------------------------------------------------
// Launch
// ---------------------------------------------------------------------------
extern "C" void kernel_launch(void* const* d_in, const int* in_sizes, int n_in,
                              void* d_out, int out_size) {
    const float* x        = (const float*)d_in[0];
    const float* W        = (const float*)d_in[1];
    const float* edge_val = (const float*)d_in[2];
    const int*   edge_src = (const int*)  d_in[3];
    const int*   edge_dst = (const int*)  d_in[4];
    float* out = (float*)d_out;

    float *PS; int *counts, *rowstart, *cursor, *partials; uint2 *payload;
    cudaGetSymbolAddress((void**)&PS,       g_presup);
    cudaGetSymbolAddress((void**)&counts,   g_counts);
    cudaGetSymbolAddress((void**)&rowstart, g_rowstart);
    cudaGetSymbolAddress((void**)&cursor,   g_cursor);
    cudaGetSymbolAddress((void**)&partials, g_partials);
    cudaGetSymbolAddress((void**)&payload,  g_payload);

    static bool attr_set = false;
    if (!attr_set) {
        cudaFuncSetAttribute(gemm_mma_kernel,
                             cudaFuncAttributeMaxDynamicSharedMemorySize, SMEM_SZ);
        attr_set = true;
    }

    // --- CSR build ---
    zero_counts_kernel<<<(N_NODES + 255) / 256, 256>>>(counts);
    hist_kernel<<<(TOT_E + 255) / 256, 256>>>(edge_dst, counts);
    scan_block_sums<<<SCAN_BLOCKS, 256>>>(counts, partials);
    scan_partials_kernel<<<1, 128>>>(partials);
    scan_final_kernel<<<SCAN_BLOCKS, 1024>>>(counts, partials, rowstart, cursor);
    scatter_kernel<<<(TOT_E + 255) / 256, 256>>>(edge_val, edge_src, edge_dst, cursor, payload);

    // --- GEMM ---
    wfrag_kernel<<<(WFRAG_ELEMS + 255) / 256, 256>>>(W);
    const int n_ctas = (N_NODES / 16 + 7) / 8;   // 782
    gemm_mma_kernel<<<n_ctas, 256, SMEM_SZ>>>(x, PS);

    // --- Gather (fused spmm + relu, single store per node) ---
    gather_kernel<<<(N_NODES * 32 + 255) / 256, 256>>>(PS, rowstart, payload, out);
}